// round 1
// baseline (speedup 1.0000x reference)
#include <cuda_runtime.h>
#include <math.h>

// ---------------------------------------------------------------------------
// Matern kernel matrix: out[i][j] = var * 2^{1-nu}/Gamma(nu) * x^nu * K_nu(x),
// x = sqrt(2 nu) * dist(i,j) / lengthscale, diagonal = var.
// K_nu via trapezoid quadrature of exp(-x(cosh t - 1)) cosh(nu t) on [0,6],
// 40 points (spectrally accurate for the x-range present), with per-element
// early cutoff where the exp factor underflows fp32 (exactly 0 in both this
// kernel and the reference).
// ---------------------------------------------------------------------------

#define NQ 40
#define T_MAX 6.0
#define H_Q (T_MAX / (NQ - 1))
#define INV_H ((float)((NQ - 1) / T_MAX))
#define LOG2E 1.44269504088896340736f

__device__ float g_a2[NQ];    // (cosh t_q - 1) * log2(e)
__device__ float g_c[NQ];     // w_q * cosh(nu t_q)
__device__ float g_sc[4];     // [0]=sqrt(2nu)/l, [1]=var*exp((1-nu)ln2 - lgamma(nu)), [2]=var, [3]=nu
__device__ float g_norm[1024];

__device__ __forceinline__ float ex2f(float x) {
    float r; asm("ex2.approx.ftz.f32 %0, %1;" : "=f"(r) : "f"(x)); return r;
}
__device__ __forceinline__ float lg2f(float x) {
    float r; asm("lg2.approx.f32 %0, %1;" : "=f"(r) : "f"(x)); return r;
}

// --- prepass: quadrature tables + scalar constants (double precision) -------
__global__ void prep_kernel(const float* __restrict__ nu_p,
                            const float* __restrict__ lv_p,
                            const float* __restrict__ ll_p) {
    int t = threadIdx.x;
    double nu = (double)nu_p[0];
    if (t < NQ) {
        double tt = H_Q * (double)t;
        double w = (t == 0 || t == NQ - 1) ? 0.5 * H_Q : H_Q;
        g_a2[t] = (float)((cosh(tt) - 1.0) * 1.4426950408889634074);
        g_c[t]  = (float)(w * cosh(nu * tt));
    }
    if (t == 0) {
        double var = exp((double)lv_p[0]);
        double len = exp((double)ll_p[0]);
        g_sc[0] = (float)(sqrt(2.0 * nu) / len);
        g_sc[1] = (float)(var * exp((1.0 - nu) * 0.69314718055994530942 - lgamma(nu)));
        g_sc[2] = (float)var;
        g_sc[3] = (float)nu;
    }
}

// --- prepass: row squared norms ---------------------------------------------
__global__ void norms_kernel(const float* __restrict__ X, int N) {
    int i = blockIdx.x * blockDim.x + threadIdx.x;
    if (i < N) {
        const float4* r = (const float4*)(X + i * 32);
        float s = 0.f;
#pragma unroll
        for (int k = 0; k < 8; k++) {
            float4 v = r[k];
            s = fmaf(v.x, v.x, s);
            s = fmaf(v.y, v.y, s);
            s = fmaf(v.z, v.z, s);
            s = fmaf(v.w, v.w, s);
        }
        g_norm[i] = s;
    }
}

// --- main: one thread per output element, 16x16 tiles -----------------------
__global__ __launch_bounds__(256) void matern_main(const float* __restrict__ X,
                                                   float* __restrict__ out,
                                                   int N) {
    __shared__ float sa[NQ], sc[NQ];
    __shared__ float sxi[16][36];   // padded: stride 36 floats, 16B aligned
    __shared__ float sxj[16][36];

    const int tx = threadIdx.x, ty = threadIdx.y;
    const int tid = ty * 16 + tx;
    const int i0 = blockIdx.y * 16, j0 = blockIdx.x * 16;

    if (tid < NQ) { sa[tid] = g_a2[tid]; sc[tid] = g_c[tid]; }
    {
        const float4* Xi = (const float4*)(X + i0 * 32);
        const float4* Xj = (const float4*)(X + j0 * 32);
        if (tid < 128) {
            int r = tid >> 3, k = tid & 7;
            *(float4*)&sxi[r][4 * k] = Xi[r * 8 + k];
        } else {
            int t2 = tid - 128;
            int r = t2 >> 3, k = t2 & 7;
            *(float4*)&sxj[r][4 * k] = Xj[r * 8 + k];
        }
    }
    __syncthreads();

    // dot(x_i, x_j)
    float dot = 0.f;
#pragma unroll
    for (int k = 0; k < 8; k++) {
        float4 a = *(const float4*)&sxi[ty][4 * k];
        float4 b = *(const float4*)&sxj[tx][4 * k];
        dot = fmaf(a.x, b.x, dot);
        dot = fmaf(a.y, b.y, dot);
        dot = fmaf(a.z, b.z, dot);
        dot = fmaf(a.w, b.w, dot);
    }

    const int i = i0 + ty, j = j0 + tx;
    const float ni = g_norm[i], nj = g_norm[j];
    const float fac = g_sc[0], Cvar = g_sc[1], var_s = g_sc[2], nu_s = g_sc[3];

    float sq   = fmaxf(fmaf(-2.f, dot, ni + nj), 1e-24f);
    float dist = sqrtf(sq);
    float x    = fmaxf(fac * dist, 1e-10f);
    float mx   = -x;

    // per-element loop bound: terms with x*(cosh t - 1) > 88 underflow to 0
    float tcut = acoshf(1.f + __fdividef(88.f, x));
    int qmax = (int)(tcut * INV_H) + 2;
    qmax = min(qmax, NQ);

    float acc = 0.f;
#pragma unroll 4
    for (int q = 0; q < qmax; ++q) {
        acc = fmaf(sc[q], ex2f(mx * sa[q]), acc);
    }

    // k = Cvar * x^nu * e^{-x} * acc  =  Cvar * 2^{nu*log2(x) - x*log2(e)} * acc
    float pw = ex2f(fmaf(nu_s, lg2f(x), mx * LOG2E));
    float kv = Cvar * acc * pw;

    out[i * N + j] = (i == j) ? var_s : kv;
}

extern "C" void kernel_launch(void* const* d_in, const int* in_sizes, int n_in,
                              void* d_out, int out_size) {
    const float* X  = (const float*)d_in[0];
    const float* nu = (const float*)d_in[1];
    const float* lv = (const float*)d_in[2];
    const float* ll = (const float*)d_in[3];
    float* out = (float*)d_out;
    int N = in_sizes[0] / 32;   // 1024

    prep_kernel<<<1, 64>>>(nu, lv, ll);
    norms_kernel<<<(N + 255) / 256, 256>>>(X, N);
    dim3 grid(N / 16, N / 16), block(16, 16);
    matern_main<<<grid, block>>>(X, out, N);
}

// round 2
// speedup vs baseline: 1.0504x; 1.0504x over previous
#include <cuda_runtime.h>
#include <math.h>

// ---------------------------------------------------------------------------
// Matern kernel matrix, fully fused single launch.
// out[i][j] = var * 2^{1-nu}/Gamma(nu) * x^nu * K_nu(x),
//   x = sqrt(2 nu)*dist(i,j)/lengthscale, diagonal = var.
// K_nu via 32-pt trapezoid of exp(-x(cosh t - 1)) cosh(nu t) on [0,6], with
// per-element cutoff where the exp factor underflows fp32 (exactly 0 in both
// this kernel and the reference). Quadrature tables + scalar constants are
// recomputed per block in fp32 (cheap, parallel) instead of a serializing
// fp64 prepass kernel.
// ---------------------------------------------------------------------------

#define NQ 32
#define H_Q ((float)(6.0 / (NQ - 1)))
#define INV_H ((float)((NQ - 1) / 6.0))
#define LOG2E 1.44269504088896340736f
#define LN2   0.69314718055994530942f

__device__ __forceinline__ float ex2f(float x) {
    float r; asm("ex2.approx.ftz.f32 %0, %1;" : "=f"(r) : "f"(x)); return r;
}
__device__ __forceinline__ float lg2f(float x) {
    float r; asm("lg2.approx.f32 %0, %1;" : "=f"(r) : "f"(x)); return r;
}

__global__ __launch_bounds__(256) void matern_fused(const float* __restrict__ X,
                                                    const float* __restrict__ nu_p,
                                                    const float* __restrict__ lv_p,
                                                    const float* __restrict__ ll_p,
                                                    float* __restrict__ out,
                                                    int N) {
    __shared__ float sa[NQ];        // (cosh t_q - 1) * log2(e)
    __shared__ float sc[NQ];        // w_q * cosh(nu t_q)
    __shared__ float scon[4];       // fac, Cvar, var, nu
    __shared__ float sxi[16][36];   // padded rows (stride 36 floats)
    __shared__ float sxj[16][36];

    const int tx = threadIdx.x, ty = threadIdx.y;
    const int tid = ty * 16 + tx;
    const int i0 = blockIdx.y * 16, j0 = blockIdx.x * 16;

    // --- per-block table + constant setup (fp32) ----------------------------
    if (tid < NQ) {
        float nu = nu_p[0];
        float t  = H_Q * (float)tid;
        float sh = sinhf(0.5f * t);                       // cosh t - 1 = 2 sinh^2(t/2)
        sa[tid]  = 2.f * sh * sh * LOG2E;
        float w  = (tid == 0 || tid == NQ - 1) ? 0.5f * H_Q : H_Q;
        sc[tid]  = w * coshf(nu * t);
    } else if (tid == NQ) {
        float nu  = nu_p[0];
        float var = __expf(lv_p[0]);
        float len = __expf(ll_p[0]);
        scon[0] = sqrtf(2.f * nu) / len;
        scon[1] = var * __expf((1.f - nu) * LN2 - lgammaf(nu));
        scon[2] = var;
        scon[3] = nu;
    }

    // --- tile loads ----------------------------------------------------------
    {
        const float4* Xi = (const float4*)(X + i0 * 32);
        const float4* Xj = (const float4*)(X + j0 * 32);
        if (tid < 128) {
            int r = tid >> 3, k = tid & 7;
            *(float4*)&sxi[r][4 * k] = Xi[r * 8 + k];
        } else {
            int t2 = tid - 128;
            int r = t2 >> 3, k = t2 & 7;
            *(float4*)&sxj[r][4 * k] = Xj[r * 8 + k];
        }
    }
    __syncthreads();

    // --- squared distance directly from the tiles ----------------------------
    float sq = 0.f;
#pragma unroll
    for (int k = 0; k < 8; k++) {
        float4 a = *(const float4*)&sxi[ty][4 * k];
        float4 b = *(const float4*)&sxj[tx][4 * k];
        float dx = a.x - b.x, dy = a.y - b.y, dz = a.z - b.z, dw = a.w - b.w;
        sq = fmaf(dx, dx, sq);
        sq = fmaf(dy, dy, sq);
        sq = fmaf(dz, dz, sq);
        sq = fmaf(dw, dw, sq);
    }

    const float fac = scon[0], Cvar = scon[1], var_s = scon[2], nu_s = scon[3];

    float dist = sqrtf(fmaxf(sq, 1e-24f));
    float x    = fmaxf(fac * dist, 1e-10f);
    float mx   = -x;

    // cutoff: x*(cosh t - 1) > 88 underflows fp32. cosh t >= e^t/2 gives the
    // safe over-estimate t_cut <= ln(2*(1+88/x)) = (1 + lg2(1+88/x)) * ln2.
    float tcut = (1.f + lg2f(1.f + __fdividef(88.f, x))) * LN2;
    int qmax = min((int)(tcut * INV_H) + 2, NQ);

    float acc = 0.f;
#pragma unroll 4
    for (int q = 0; q < qmax; ++q) {
        acc = fmaf(sc[q], ex2f(mx * sa[q]), acc);
    }

    // k = Cvar * x^nu * e^{-x} * acc = Cvar * acc * 2^{nu*log2(x) - x*log2e}
    float pw = ex2f(fmaf(nu_s, lg2f(x), mx * LOG2E));
    float kv = Cvar * acc * pw;

    const int i = i0 + ty, j = j0 + tx;
    out[i * N + j] = (i == j) ? var_s : kv;
}

extern "C" void kernel_launch(void* const* d_in, const int* in_sizes, int n_in,
                              void* d_out, int out_size) {
    const float* X  = (const float*)d_in[0];
    const float* nu = (const float*)d_in[1];
    const float* lv = (const float*)d_in[2];
    const float* ll = (const float*)d_in[3];
    float* out = (float*)d_out;
    int N = in_sizes[0] / 32;   // 1024

    dim3 grid(N / 16, N / 16), block(16, 16);
    matern_fused<<<grid, block>>>(X, nu, lv, ll, out, N);
}

// round 3
// speedup vs baseline: 2.0467x; 1.9484x over previous
#include <cuda_runtime.h>
#include <math.h>

// ---------------------------------------------------------------------------
// Matern kernel matrix via tabulated log2(C * x^nu * K_nu(x)).
//
// Kernel 1 (build_table): L[k] = log2( C * x_k^nu * e^{-x_k} * S(x_k) ),
//   S(x) = trapezoid_{[0,6],48pt} exp(-x(cosh t - 1)) cosh(nu t)  -- same
//   integral form as the reference (spectrally converged for all x queried).
//   Stored as float2 {L_k, L_{k+1}} -> single LDG.64 lookup.
// Kernel 2 (matern_main): dist^2 via norms + dot (reference formula), then
//   x = fac*dist, linear interp of L in log2 domain, one ex2. Triangular
//   block decomposition, mirror tile written via smem transpose.
// ---------------------------------------------------------------------------

#define TBL_N   4096
#define TBL_XMAX 96.0f
#define TBL_DX  (TBL_XMAX / TBL_N)
#define TBL_INVDX (TBL_N / TBL_XMAX)

#define NQT 48
#define HQT (6.0f / (NQT - 1))

#define LOG2E 1.44269504088896340736f

__device__ float2 g_tbl[TBL_N + 2];   // {L_k, L_{k+1}}
__device__ float  g_fac;              // sqrt(2 nu) / lengthscale
__device__ float  g_var;              // variance

__device__ __forceinline__ float ex2f(float x) {
    float r; asm("ex2.approx.ftz.f32 %0, %1;" : "=f"(r) : "f"(x)); return r;
}
__device__ __forceinline__ float lg2f(float x) {
    float r; asm("lg2.approx.f32 %0, %1;" : "=f"(r) : "f"(x)); return r;
}

// --- kernel 1: table build (8 lanes per entry, 32 entries per 256-thr block)
__global__ __launch_bounds__(256) void build_table(const float* __restrict__ nu_p,
                                                   const float* __restrict__ lv_p,
                                                   const float* __restrict__ ll_p) {
    __shared__ float s_log2C, s_nu;
    if (threadIdx.x == 0) {
        float nu = nu_p[0];
        s_nu = nu;
        // log2(var * 2^{1-nu} / Gamma(nu))
        s_log2C = lv_p[0] * LOG2E + (1.f - nu) - lgammaf(nu) * LOG2E;
        if (blockIdx.x == 0) {
            g_fac = sqrtf(2.f * nu) * __expf(-ll_p[0]);
            g_var = __expf(lv_p[0]);
        }
    }
    __syncthreads();

    const float nu = s_nu;
    const int k    = blockIdx.x * 32 + (threadIdx.x >> 3);
    const int lane = threadIdx.x & 7;
    const float x  = TBL_DX * (float)k;

    // partial quadrature sum: points q = lane + 8*m, m = 0..5
    float S = 0.f;
#pragma unroll
    for (int m = 0; m < 6; m++) {
        int q   = lane + 8 * m;
        float t = HQT * (float)q;
        float w = (q == 0 || q == NQT - 1) ? 0.5f * HQT : HQT;
        float a = (coshf(t) - 1.f) * LOG2E;
        S += (w * coshf(nu * t)) * ex2f(-x * a);
    }
    S += __shfl_xor_sync(0xffffffffu, S, 1);
    S += __shfl_xor_sync(0xffffffffu, S, 2);
    S += __shfl_xor_sync(0xffffffffu, S, 4);

    if (lane == 0 && k <= TBL_N) {
        float L = s_log2C + nu * lg2f(x) - x * LOG2E + lg2f(S);
        L = fmaxf(L, -150.f);            // x=0 -> -inf; clamp (ex2 -> 0)
        g_tbl[k].x = L;
        if (k > 0) g_tbl[k - 1].y = L;
    }
}

// --- kernel 2: main, triangular tiles -----------------------------------
__global__ __launch_bounds__(256) void matern_main(const float* __restrict__ X,
                                                   float* __restrict__ out,
                                                   int N) {
    __shared__ float sxi[16][36];
    __shared__ float sxj[16][36];
    __shared__ float sni[16], snj[16];
    __shared__ float sval[16][17];
    __shared__ float sfac, svar;

    const int tid = threadIdx.x;
    const int tx = tid & 15, ty = tid >> 4;

    // triangular block index -> (bi, bj), bi <= bj
    const int B = N >> 4;
    const int p = blockIdx.x;
    int bi = (int)(((float)(2 * B + 1) -
                    sqrtf((float)((2 * B + 1) * (2 * B + 1) - 8 * p))) * 0.5f);
    while (bi * (2 * B - bi + 1) / 2 > p) bi--;
    while ((bi + 1) * (2 * B - bi) / 2 <= p) bi++;
    const int bj = bi + (p - bi * (2 * B - bi + 1) / 2);
    const int i0 = bi * 16, j0 = bj * 16;

    // tile loads
    {
        const float4* Xi = (const float4*)(X + i0 * 32);
        const float4* Xj = (const float4*)(X + j0 * 32);
        if (tid < 128) {
            int r = tid >> 3, k = tid & 7;
            *(float4*)&sxi[r][4 * k] = Xi[r * 8 + k];
        } else {
            int t2 = tid - 128;
            int r = t2 >> 3, k = t2 & 7;
            *(float4*)&sxj[r][4 * k] = Xj[r * 8 + k];
        }
    }
    if (tid == 0) { sfac = g_fac; svar = g_var; }
    __syncthreads();

    // row norms (threads 0..31, one row each)
    if (tid < 32) {
        const float* row = (tid < 16) ? sxi[tid] : sxj[tid - 16];
        float s = 0.f;
#pragma unroll
        for (int k = 0; k < 32; k++) s = fmaf(row[k], row[k], s);
        if (tid < 16) sni[tid] = s; else snj[tid - 16] = s;
    }
    __syncthreads();

    // dot(x_i, x_j)
    float dot = 0.f;
#pragma unroll
    for (int k = 0; k < 8; k++) {
        float4 a = *(const float4*)&sxi[ty][4 * k];
        float4 b = *(const float4*)&sxj[tx][4 * k];
        dot = fmaf(a.x, b.x, dot);
        dot = fmaf(a.y, b.y, dot);
        dot = fmaf(a.z, b.z, dot);
        dot = fmaf(a.w, b.w, dot);
    }

    float sq   = fmaxf(fmaf(-2.f, dot, sni[ty] + snj[tx]), 1e-24f);
    float x    = fmaxf(sfac * sqrtf(sq), 1e-10f);

    // table interp in log2 domain
    float u  = fminf(x * TBL_INVDX, (float)TBL_N - 0.001f);
    int   kk = (int)u;
    float f  = u - (float)kk;
    float2 Lp = g_tbl[kk];
    float val = ex2f(fmaf(f, Lp.y - Lp.x, Lp.x));

    const int i = i0 + ty, j = j0 + tx;
    val = (i == j) ? svar : val;

    out[i * N + j] = val;

    // mirror tile via smem transpose (coalesced)
    if (bi != bj) {
        sval[ty][tx] = val;
        __syncthreads();
        out[(j0 + ty) * N + (i0 + tx)] = sval[tx][ty];
    }
}

extern "C" void kernel_launch(void* const* d_in, const int* in_sizes, int n_in,
                              void* d_out, int out_size) {
    const float* X  = (const float*)d_in[0];
    const float* nu = (const float*)d_in[1];
    const float* lv = (const float*)d_in[2];
    const float* ll = (const float*)d_in[3];
    float* out = (float*)d_out;
    const int N = in_sizes[0] / 32;   // 1024

    build_table<<<(TBL_N + 32) / 32, 256>>>(nu, lv, ll);

    const int B = N / 16;
    matern_main<<<B * (B + 1) / 2, 256>>>(X, out, N);
}

// round 5
// speedup vs baseline: 2.0825x; 1.0175x over previous
#include <cuda_runtime.h>
#include <math.h>

// ---------------------------------------------------------------------------
// Matern kernel matrix via tabulated L(x) = log2(C * x^nu * K_nu(x)).
// Kernel 1 builds a 1025-entry table over x in [0,96] (48-pt trapezoid of the
// reference's integral representation, spectrally converged).
// Kernel 2: 64x64 tiles, 256 threads, 4x4 register micro-tile per thread,
// smem-resident table, triangular block decomposition + smem transpose mirror.
// Smem tile rows padded to 36 floats (multiple of 4 -> float4-aligned rows).
// ---------------------------------------------------------------------------

#define TBL_N    1024
#define TBL_XMAX 96.0f
#define TBL_DX   (TBL_XMAX / TBL_N)
#define TBL_INVDX ((float)TBL_N / TBL_XMAX)

#define NQT 48
#define HQT (6.0f / (NQT - 1))
#define LOG2E 1.44269504088896340736f

__device__ float2 g_tbl[TBL_N + 2];   // {L_k, L_{k+1}}
__device__ float  g_fac;              // sqrt(2 nu) / lengthscale
__device__ float  g_var;              // variance

__device__ __forceinline__ float ex2f(float x) {
    float r; asm("ex2.approx.ftz.f32 %0, %1;" : "=f"(r) : "f"(x)); return r;
}
__device__ __forceinline__ float lg2f(float x) {
    float r; asm("lg2.approx.f32 %0, %1;" : "=f"(r) : "f"(x)); return r;
}

// --- kernel 1: table build (8 lanes per entry, 32 entries per block) --------
__global__ __launch_bounds__(256) void build_table(const float* __restrict__ nu_p,
                                                   const float* __restrict__ lv_p,
                                                   const float* __restrict__ ll_p) {
    __shared__ float s_log2C, s_nu;
    if (threadIdx.x == 0) {
        float nu = nu_p[0];
        s_nu = nu;
        s_log2C = lv_p[0] * LOG2E + (1.f - nu) - lgammaf(nu) * LOG2E;
        if (blockIdx.x == 0) {
            g_fac = sqrtf(2.f * nu) * __expf(-ll_p[0]);
            g_var = __expf(lv_p[0]);
        }
    }
    __syncthreads();

    const float nu = s_nu;
    const int k    = blockIdx.x * 32 + (threadIdx.x >> 3);
    const int lane = threadIdx.x & 7;
    const float x  = TBL_DX * (float)k;

    float S = 0.f;
#pragma unroll
    for (int m = 0; m < 6; m++) {
        int q   = lane + 8 * m;
        float t = HQT * (float)q;
        float w = (q == 0 || q == NQT - 1) ? 0.5f * HQT : HQT;
        float a = (coshf(t) - 1.f) * LOG2E;
        S += (w * coshf(nu * t)) * ex2f(-x * a);
    }
    S += __shfl_xor_sync(0xffffffffu, S, 1);
    S += __shfl_xor_sync(0xffffffffu, S, 2);
    S += __shfl_xor_sync(0xffffffffu, S, 4);

    if (lane == 0 && k <= TBL_N) {
        float L = s_log2C + nu * lg2f(x) - x * LOG2E + lg2f(S);
        L = fmaxf(L, -150.f);
        g_tbl[k].x = L;
        if (k > 0) g_tbl[k - 1].y = L;
    }
}

// --- kernel 2: 64x64 tiles, 4x4 micro-tile ----------------------------------
__global__ __launch_bounds__(256) void matern_main(const float* __restrict__ X,
                                                   float* __restrict__ out,
                                                   int N) {
    __shared__ float  sxi[64][36];     // stride multiple of 4 floats (16B)
    __shared__ float  sxj[64][36];
    __shared__ float  sni[64], snj[64];
    __shared__ float2 stbl[TBL_N + 1];
    __shared__ float  strans[64][65];
    __shared__ float  sfac, svar;

    const int tid = threadIdx.x;
    const int tx = tid & 15, ty = tid >> 4;

    // triangular block index -> (bi, bj), bi <= bj  (B = 16, cheap loop)
    const int B = N >> 6;
    int bi = 0, rem = blockIdx.x;
    while (rem >= B - bi) { rem -= (B - bi); bi++; }
    const int bj = bi + rem;
    const int i0 = bi * 64, j0 = bj * 64;

    // tile loads: 512 float4 per tile, 2 per thread
    {
        const float4* Xi = (const float4*)(X + i0 * 32);
        const float4* Xj = (const float4*)(X + j0 * 32);
#pragma unroll
        for (int m = 0; m < 2; m++) {
            int idx = m * 256 + tid;          // 0..511
            int r = idx >> 3, k = idx & 7;
            *(float4*)&sxi[r][4 * k] = Xi[idx];
            *(float4*)&sxj[r][4 * k] = Xj[idx];
        }
    }
    // table copy to smem
    for (int idx = tid; idx <= TBL_N; idx += 256) stbl[idx] = g_tbl[idx];
    if (tid == 0) { sfac = g_fac; svar = g_var; }
    __syncthreads();

    // row norms
    if (tid < 128) {
        int r = tid & 63;
        const float* row = (tid < 64) ? sxi[r] : sxj[r];
        float s = 0.f;
#pragma unroll
        for (int k = 0; k < 32; k++) s = fmaf(row[k], row[k], s);
        if (tid < 64) sni[r] = s; else snj[r] = s;
    }
    __syncthreads();

    // 4x4 register micro-tile dot products
    float acc[4][4];
#pragma unroll
    for (int r = 0; r < 4; r++)
#pragma unroll
        for (int c = 0; c < 4; c++) acc[r][c] = 0.f;

#pragma unroll
    for (int kc = 0; kc < 8; kc++) {
        float4 a[4], b[4];
#pragma unroll
        for (int r = 0; r < 4; r++) a[r] = *(const float4*)&sxi[ty * 4 + r][kc * 4];
#pragma unroll
        for (int c = 0; c < 4; c++) b[c] = *(const float4*)&sxj[tx * 4 + c][kc * 4];
#pragma unroll
        for (int r = 0; r < 4; r++)
#pragma unroll
            for (int c = 0; c < 4; c++) {
                acc[r][c] = fmaf(a[r].x, b[c].x, acc[r][c]);
                acc[r][c] = fmaf(a[r].y, b[c].y, acc[r][c]);
                acc[r][c] = fmaf(a[r].z, b[c].z, acc[r][c]);
                acc[r][c] = fmaf(a[r].w, b[c].w, acc[r][c]);
            }
    }

    const float fac = sfac, var_s = svar;
    float ni[4], nj[4];
#pragma unroll
    for (int r = 0; r < 4; r++) ni[r] = sni[ty * 4 + r];
#pragma unroll
    for (int c = 0; c < 4; c++) nj[c] = snj[tx * 4 + c];

    const int i_base = i0 + ty * 4, j_base = j0 + tx * 4;
    const bool offdiag = (bi != bj);

#pragma unroll
    for (int r = 0; r < 4; r++) {
        float4 v;
#pragma unroll
        for (int c = 0; c < 4; c++) {
            float sq = fmaxf(fmaf(-2.f, acc[r][c], ni[r] + nj[c]), 1e-24f);
            float x  = fmaxf(fac * sqrtf(sq), 1e-10f);
            float u  = fminf(x * TBL_INVDX, (float)TBL_N - 0.001f);
            int   kk = (int)u;
            float f  = u - (float)kk;
            float2 Lp = stbl[kk];
            float val = ex2f(fmaf(f, Lp.y - Lp.x, Lp.x));
            if (i_base + r == j_base + c) val = var_s;
            ((float*)&v)[c] = val;
            if (offdiag) strans[tx * 4 + c][ty * 4 + r] = val;
        }
        *(float4*)&out[(i_base + r) * N + j_base] = v;
    }

    // mirror tile (coalesced via smem transpose)
    if (offdiag) {
        __syncthreads();
#pragma unroll
        for (int m = 0; m < 16; m++) {
            int idx = m * 256 + tid;
            int jj = idx >> 6, ii = idx & 63;
            out[(j0 + jj) * N + (i0 + ii)] = strans[jj][ii];
        }
    }
}

extern "C" void kernel_launch(void* const* d_in, const int* in_sizes, int n_in,
                              void* d_out, int out_size) {
    const float* X  = (const float*)d_in[0];
    const float* nu = (const float*)d_in[1];
    const float* lv = (const float*)d_in[2];
    const float* ll = (const float*)d_in[3];
    float* out = (float*)d_out;
    const int N = in_sizes[0] / 32;   // 1024

    build_table<<<(TBL_N + 1 + 31) / 32, 256>>>(nu, lv, ll);

    const int B = N / 64;
    matern_main<<<B * (B + 1) / 2, 256>>>(X, out, N);
}